// round 8
// baseline (speedup 1.0000x reference)
#include <cuda_runtime.h>
#include <cuda_bf16.h>
#include <math.h>
#include <stdint.h>

#define B_   4
#define N_   2048
#define KD_  129
#define H_   8
#define DO_  64
#define AD_  65
#define BH_  (B_*H_)
#define EPS_ 1e-7f
#define MUP_ 68
#define KP_  144

// ---------------- scratch ----------------------------------------------------
__device__ __nv_bfloat16 g_Xb[B_*N_*KP_];
__device__ __nv_bfloat16 g_Wb[24*DO_*KP_];
__device__ __nv_bfloat16 g_Qb[BH_*N_*64];
__device__ __nv_bfloat16 g_Kb[BH_*N_*64];
__device__ float         g_Q0[BH_*N_];
__device__ float         g_KV0[BH_*N_*2];        // (k_time, v_time) fp32 pairs
__device__ __nv_bfloat16 g_Vt[BH_*64*N_];        // V^T spatial only [bh][64][N]
__device__ float         g_Mu[BH_*N_*MUP_];

// ---------------- helpers ----------------------------------------------------
__device__ __forceinline__ uint32_t smem_u32(const void* p) {
    uint32_t a;
    asm("{ .reg .u64 t; cvta.to.shared.u64 t, %1; cvt.u32.u64 %0, t; }" : "=r"(a) : "l"(p));
    return a;
}
__device__ __forceinline__ void cpa16(uint32_t dst, const void* src) {
    asm volatile("cp.async.cg.shared.global [%0], [%1], 16;" :: "r"(dst), "l"(src));
}
#define CP_COMMIT() asm volatile("cp.async.commit_group;" ::: "memory")
#define CP_WAIT0()  asm volatile("cp.async.wait_group 0;" ::: "memory")
#define CP_WAIT2()  asm volatile("cp.async.wait_group 2;" ::: "memory")

__device__ __forceinline__ void mma16816(float* d,
    uint32_t a0, uint32_t a1, uint32_t a2, uint32_t a3,
    uint32_t b0, uint32_t b1)
{
    asm volatile("mma.sync.aligned.m16n8k16.row.col.f32.bf16.bf16.f32 "
        "{%0,%1,%2,%3}, {%4,%5,%6,%7}, {%8,%9}, {%0,%1,%2,%3};"
        : "+f"(d[0]), "+f"(d[1]), "+f"(d[2]), "+f"(d[3])
        : "r"(a0), "r"(a1), "r"(a2), "r"(a3), "r"(b0), "r"(b1));
}
__device__ __forceinline__ void ldm_x4(uint32_t& r0, uint32_t& r1,
                                       uint32_t& r2, uint32_t& r3, uint32_t a)
{
    asm volatile("ldmatrix.sync.aligned.m8n8.x4.shared.b16 {%0,%1,%2,%3}, [%4];"
        : "=r"(r0), "=r"(r1), "=r"(r2), "=r"(r3) : "r"(a));
}
__device__ __forceinline__ float ex2f(float x) {
    float r; asm("ex2.approx.ftz.f32 %0, %1;" : "=f"(r) : "f"(x)); return r;
}
__device__ __forceinline__ uint32_t bf2(float lo, float hi) {
    uint32_t r; asm("cvt.rn.bf16x2.f32 %0, %1, %2;" : "=r"(r) : "f"(hi), "f"(lo)); return r;
}

// ---------------- prep --------------------------------------------------------
__global__ __launch_bounds__(256) void prep_kernel(
    const float* __restrict__ x,
    const float* __restrict__ Wq, const float* __restrict__ Wk,
    const float* __restrict__ Wv)
{
    const int nt = gridDim.x * 256;
    const int t0 = blockIdx.x * 256 + threadIdx.x;

    for (int i = t0; i < B_*N_*KP_; i += nt) {
        int bn = i / KP_, c = i - bn * KP_;
        g_Xb[i] = __float2bfloat16_rn(c < KD_ ? x[(size_t)bn * KD_ + c] : 0.f);
    }
    for (int i = t0; i < 24*DO_*KP_; i += nt) {
        int idx = i / (DO_*KP_);
        int r   = i - idx * (DO_*KP_);
        int d   = r / KP_, k = r - d * KP_;
        int m = idx >> 3, h = idx & 7;
        const float* W = (m == 0 ? Wq : (m == 1 ? Wk : Wv)) + h * KD_ * DO_;
        g_Wb[i] = __float2bfloat16_rn(k < KD_ ? W[k * DO_ + d] : 0.f);
    }
}

// ---------------- projection v2: one CTA does Q,K,V for one (n0,h,b) ---------
// X loaded once; 3 W tiles prefetched upfront; ldmatrix A+B fragments.
#define PX_ST 76                          // words per row (304 B)
#define PROJ_XS_B (128*PX_ST*4)           // 38912
#define PROJ_W1_B (64*PX_ST*4)            // 19456
#define PROJ_SMEM (PROJ_XS_B + 3*PROJ_W1_B)   // 97280
#define TS_ST 136

__global__ __launch_bounds__(256, 2) void proj_kernel(
    const float* __restrict__ bq, const float* __restrict__ bk,
    const float* __restrict__ bv)
{
    extern __shared__ char smem[];
    const uint32_t sb = smem_u32(smem);
    const int tid = threadIdx.x, wid = tid >> 5, lane = tid & 31;
    const int n0 = blockIdx.x * 128;
    const int h  = blockIdx.y;
    const int b  = blockIdx.z;
    const int bh = b * H_ + h;

    const __nv_bfloat16* Xg = g_Xb + (size_t)b * N_ * KP_;

    // loads: X tile + 3 W tiles, one group
    for (int i = tid; i < 128 * 18; i += 256) {
        int r = i / 18, c = i - r * 18;
        cpa16(sb + r * 304 + c * 16, Xg + (size_t)(n0 + r) * KP_ + c * 8);
    }
    #pragma unroll
    for (int m = 0; m < 3; m++) {
        const __nv_bfloat16* Wg = g_Wb + (size_t)(m * 8 + h) * DO_ * KP_;
        for (int i = tid; i < 64 * 18; i += 256) {
            int r = i / 18, c = i - r * 18;
            cpa16(sb + PROJ_XS_B + m * PROJ_W1_B + r * 304 + c * 16,
                  Wg + (size_t)r * KP_ + c * 8);
        }
    }
    CP_COMMIT();
    CP_WAIT0();
    __syncthreads();

    const int r0 = wid * 16;
    const int lq = lane >> 2, lm = lane & 3;
    // ldmatrix lane offsets
    const uint32_t offA = (uint32_t)((lane & 7) + ((lane >> 3) & 1) * 8) * 304u
                        + ((lane >> 4) & 1) * 16u;
    const uint32_t offB = (uint32_t)((lane & 7) + ((lane >> 4) & 1) * 8) * 304u
                        + ((lane >> 3) & 1) * 16u;
    const uint32_t xa_base = sb + r0 * 304 + offA;

    #pragma unroll
    for (int m = 0; m < 3; m++) {
        const float* bias = (m == 0 ? bq : (m == 1 ? bk : bv)) + h * DO_;
        const uint32_t wb_base = sb + PROJ_XS_B + m * PROJ_W1_B + offB;

        float o[8][4];
        #pragma unroll
        for (int jt = 0; jt < 8; jt++) {
            float b0v = bias[jt * 8 + 2 * lm];
            float b1v = bias[jt * 8 + 2 * lm + 1];
            o[jt][0] = b0v; o[jt][1] = b1v; o[jt][2] = b0v; o[jt][3] = b1v;
        }

        #pragma unroll
        for (int ks = 0; ks < 9; ks++) {
            uint32_t a0, a1, a2, a3;
            ldm_x4(a0, a1, a2, a3, xa_base + ks * 32);
            #pragma unroll
            for (int p = 0; p < 4; p++) {
                uint32_t b0, b1, b2, b3;
                ldm_x4(b0, b1, b2, b3, wb_base + p * (16 * 304) + ks * 32);
                mma16816(o[2*p],   a0, a1, a2, a3, b0, b1);
                mma16816(o[2*p+1], a0, a1, a2, a3, b2, b3);
            }
        }

        float rs0 = 0.f, rs1 = 0.f;
        #pragma unroll
        for (int jt = 0; jt < 8; jt++) {
            rs0 += o[jt][0]*o[jt][0] + o[jt][1]*o[jt][1];
            rs1 += o[jt][2]*o[jt][2] + o[jt][3]*o[jt][3];
        }
        rs0 += __shfl_xor_sync(0xffffffffu, rs0, 1);
        rs0 += __shfl_xor_sync(0xffffffffu, rs0, 2);
        rs1 += __shfl_xor_sync(0xffffffffu, rs1, 1);
        rs1 += __shfl_xor_sync(0xffffffffu, rs1, 2);
        const float t0v = sqrtf(1.0f + rs0);
        const float t1v = sqrtf(1.0f + rs1);

        const int nA = n0 + r0 + lq, nB = nA + 8;

        if (m < 2) {
            __nv_bfloat16* gb = (m == 0 ? g_Qb : g_Kb) + (size_t)bh * N_ * 64;
            #pragma unroll
            for (int jt = 0; jt < 8; jt++) {
                *(uint32_t*)(gb + (size_t)nA * 64 + jt * 8 + 2 * lm) = bf2(o[jt][0], o[jt][1]);
                *(uint32_t*)(gb + (size_t)nB * 64 + jt * 8 + 2 * lm) = bf2(o[jt][2], o[jt][3]);
            }
            if (lm == 0) {
                if (m == 0) {
                    g_Q0[(size_t)bh * N_ + nA] = t0v;
                    g_Q0[(size_t)bh * N_ + nB] = t1v;
                } else {
                    g_KV0[((size_t)bh * N_ + nA) * 2] = t0v;
                    g_KV0[((size_t)bh * N_ + nB) * 2] = t1v;
                }
            }
        } else {
            __syncthreads();   // X + all W dead -> transpose staging in X area
            __nv_bfloat16* Ts = (__nv_bfloat16*)smem;
            const int rA = r0 + lq, rB = rA + 8;
            #pragma unroll
            for (int jt = 0; jt < 8; jt++) {
                int c0 = jt * 8 + 2 * lm;
                Ts[c0 * TS_ST + rA]       = __float2bfloat16_rn(o[jt][0]);
                Ts[(c0 + 1) * TS_ST + rA] = __float2bfloat16_rn(o[jt][1]);
                Ts[c0 * TS_ST + rB]       = __float2bfloat16_rn(o[jt][2]);
                Ts[(c0 + 1) * TS_ST + rB] = __float2bfloat16_rn(o[jt][3]);
            }
            if (lm == 0) {
                g_KV0[((size_t)bh * N_ + nA) * 2 + 1] = t0v;
                g_KV0[((size_t)bh * N_ + nB) * 2 + 1] = t1v;
            }
            __syncthreads();

            __nv_bfloat16* gv = g_Vt + (size_t)bh * 64 * N_;
            for (int i = tid; i < 64 * 16; i += 256) {
                int a = i >> 4, ch = i & 15;
                uint4 v = *(const uint4*)(Ts + a * TS_ST + ch * 8);
                *(uint4*)(gv + (size_t)a * N_ + n0 + ch * 8) = v;
            }
        }
    }
}

// ---------------- attention (round-7 proven, unchanged) -----------------------
#define OFF_Q    0
#define OFF_AQ0  18432
#define OFF_ST   18944
#define STG_V    9216
#define STG_KV0  18432
#define STG_SZ   18944
#define ATTN_SMEM (OFF_ST + 4*STG_SZ)

__global__ __launch_bounds__(256, 2) void attn_kernel(const float* __restrict__ scale_p)
{
    extern __shared__ char smem[];
    const uint32_t sb = smem_u32(smem);
    const int tid = threadIdx.x, wid = tid >> 5, lane = tid & 31;
    const int bh  = blockIdx.y;
    const int q0g = blockIdx.x * 128;

    const __nv_bfloat16* Qg = g_Qb + (size_t)bh * N_ * 64;
    const __nv_bfloat16* Kg = g_Kb + (size_t)bh * N_ * 64;
    const __nv_bfloat16* Vg = g_Vt + (size_t)bh * 64 * N_;
    const float* kv0 = g_KV0 + (size_t)bh * N_ * 2;

    const float a2c = 2.0f * 1.4426950408889634f / (scale_p[0] + EPS_);

    for (int i = tid; i < 1024; i += 256) {
        int r = i >> 3, c = i & 7;
        cpa16(sb + OFF_Q + r * 144 + c * 16, Qg + (size_t)(q0g + r) * 64 + c * 8);
    }
    #pragma unroll
    for (int st = 0; st < 3; st++) {
        const int j0 = st * 64;
        const uint32_t stg = sb + OFF_ST + st * STG_SZ;
        for (int i = tid; i < 512; i += 256) {
            int r = i >> 3, c = i & 7;
            cpa16(stg + r * 144 + c * 16, Kg + (size_t)(j0 + r) * 64 + c * 8);
        }
        for (int i = tid; i < 512; i += 256) {
            int a = i >> 3, c = i & 7;
            cpa16(stg + STG_V + a * 144 + c * 16, Vg + (size_t)a * N_ + j0 + c * 8);
        }
        if (tid < 32) cpa16(stg + STG_KV0 + tid * 16, kv0 + (size_t)j0 * 2 + tid * 4);
        CP_COMMIT();
    }
    if (tid < 128)
        ((float*)(smem + OFF_AQ0))[tid] = a2c * g_Q0[(size_t)bh * N_ + q0g + tid];

    CP_WAIT2();
    __syncthreads();

    const int r0 = wid * 16;
    const int lq = lane >> 2, lm = lane & 3;
    const uint32_t offl =
        (uint32_t)((((lane >> 3) & 2) ? 8 : 0) + (lane & 7)) * 144u
        + (((lane >> 3) & 1) ? 16u : 0u);

    uint32_t qf[4][4];
    {
        const uint32_t* QSw = (const uint32_t*)(smem + OFF_Q);
        #pragma unroll
        for (int ks = 0; ks < 4; ks++) {
            const int dw = ks * 8 + lm;
            qf[ks][0] = QSw[(r0 + lq) * 36 + dw];
            qf[ks][1] = QSw[(r0 + lq + 8) * 36 + dw];
            qf[ks][2] = QSw[(r0 + lq) * 36 + dw + 4];
            qf[ks][3] = QSw[(r0 + lq + 8) * 36 + dw + 4];
        }
    }
    const float aq0 = ((const float*)(smem + OFF_AQ0))[r0 + lq];
    const float aq1 = ((const float*)(smem + OFF_AQ0))[r0 + lq + 8];

    float o[8][4];
    #pragma unroll
    for (int at = 0; at < 8; at++)
        #pragma unroll
        for (int c = 0; c < 4; c++) o[at][c] = 0.f;
    float lsum0 = 0.f, lsum1 = 0.f, tac0 = 0.f, tac1 = 0.f;

    for (int t = 0; t < 32; t++) {
        if (t) { CP_WAIT2(); __syncthreads(); }
        const uint32_t stgo = OFF_ST + (t & 3) * STG_SZ;
        const uint32_t ks_base = sb + stgo + offl;
        const uint32_t vs_base = sb + stgo + STG_V + offl;

        float s[8][4];
        #pragma unroll
        for (int jt = 0; jt < 8; jt++)
            #pragma unroll
            for (int c = 0; c < 4; c++) s[jt][c] = 0.f;

        #pragma unroll
        for (int ks = 0; ks < 4; ks++) {
            #pragma unroll
            for (int q = 0; q < 4; q++) {
                uint32_t b0, b1, b2, b3;
                ldm_x4(b0, b1, b2, b3, ks_base + q * 2304 + ks * 32);
                mma16816(s[2*q],   qf[ks][0], qf[ks][1], qf[ks][2], qf[ks][3], b0, b1);
                mma16816(s[2*q+1], qf[ks][0], qf[ks][1], qf[ks][2], qf[ks][3], b2, b3);
            }
        }

        const float2* kvs = (const float2*)(smem + stgo + STG_KV0);
        uint32_t pf[8][2];
        #pragma unroll
        for (int jt = 0; jt < 8; jt++) {
            const float2 kva = kvs[jt * 8 + 2 * lm];
            const float2 kvb = kvs[jt * 8 + 2 * lm + 1];
            float p0 = ex2f(fmaf(a2c, s[jt][0], -aq0 * kva.x));
            float p1 = ex2f(fmaf(a2c, s[jt][1], -aq0 * kvb.x));
            float p2 = ex2f(fmaf(a2c, s[jt][2], -aq1 * kva.x));
            float p3 = ex2f(fmaf(a2c, s[jt][3], -aq1 * kvb.x));
            lsum0 += p0 + p1;  lsum1 += p2 + p3;
            tac0  = fmaf(p0, kva.y, fmaf(p1, kvb.y, tac0));
            tac1  = fmaf(p2, kva.y, fmaf(p3, kvb.y, tac1));
            pf[jt][0] = bf2(p0, p1);
            pf[jt][1] = bf2(p2, p3);
        }

        #pragma unroll
        for (int kt = 0; kt < 4; kt++) {
            const uint32_t A0 = pf[2*kt][0], A1 = pf[2*kt][1];
            const uint32_t A2 = pf[2*kt+1][0], A3 = pf[2*kt+1][1];
            #pragma unroll
            for (int p = 0; p < 4; p++) {
                uint32_t b0, b1, b2, b3;
                ldm_x4(b0, b1, b2, b3, vs_base + p * 2304 + kt * 32);
                mma16816(o[2*p],   A0, A1, A2, A3, b0, b1);
                mma16816(o[2*p+1], A0, A1, A2, A3, b2, b3);
            }
        }

        if (t + 3 < 32) {
            const int j0 = (t + 3) * 64;
            const uint32_t pstg = sb + OFF_ST + ((t + 3) & 3) * STG_SZ;
            for (int i = tid; i < 512; i += 256) {
                int r = i >> 3, c = i & 7;
                cpa16(pstg + r * 144 + c * 16, Kg + (size_t)(j0 + r) * 64 + c * 8);
            }
            for (int i = tid; i < 512; i += 256) {
                int a = i >> 3, c = i & 7;
                cpa16(pstg + STG_V + a * 144 + c * 16, Vg + (size_t)a * N_ + j0 + c * 8);
            }
            if (tid < 32) cpa16(pstg + STG_KV0 + tid * 16, kv0 + (size_t)j0 * 2 + tid * 4);
        }
        CP_COMMIT();
    }

    lsum0 += __shfl_xor_sync(0xffffffffu, lsum0, 1);
    lsum0 += __shfl_xor_sync(0xffffffffu, lsum0, 2);
    lsum1 += __shfl_xor_sync(0xffffffffu, lsum1, 1);
    lsum1 += __shfl_xor_sync(0xffffffffu, lsum1, 2);
    tac0  += __shfl_xor_sync(0xffffffffu, tac0, 1);
    tac0  += __shfl_xor_sync(0xffffffffu, tac0, 2);
    tac1  += __shfl_xor_sync(0xffffffffu, tac1, 1);
    tac1  += __shfl_xor_sync(0xffffffffu, tac1, 2);
    const float inv0 = 1.0f / lsum0;
    const float inv1 = 1.0f / lsum1;

    float* mA = g_Mu + ((size_t)bh * N_ + q0g + r0 + lq) * MUP_;
    float* mB = mA + 8 * MUP_;
    #pragma unroll
    for (int at = 0; at < 8; at++) {
        const int c = at * 8 + 2 * lm;
        mA[c + 1] = o[at][0] * inv0;  mA[c + 2] = o[at][1] * inv0;
        mB[c + 1] = o[at][2] * inv1;  mB[c + 2] = o[at][3] * inv1;
    }
    if (lm == 0) { mA[0] = tac0 * inv0; mB[0] = tac1 * inv1; }
}

// ---------------- finalize ----------------------------------------------------
__global__ __launch_bounds__(256) void finalize_kernel(float* __restrict__ out)
{
    const int gw = (blockIdx.x * blockDim.x + threadIdx.x) >> 5;
    const int lane = threadIdx.x & 31;
    if (gw >= B_ * N_) return;
    const int b = gw >> 11, n = gw & (N_ - 1);

    float a0 = 0.f, a1 = 0.f, a2 = 0.f;
    for (int h = 0; h < H_; h++) {
        const float* mu = g_Mu + ((size_t)(b * H_ + h) * N_ + n) * MUP_;
        float m0 = mu[lane];
        float m1 = mu[lane + 32];
        float m2 = (lane == 0) ? mu[64] : 0.f;
        float ss = m0 * m0 + m1 * m1 + m2 * m2;
        #pragma unroll
        for (int o = 16; o; o >>= 1) ss += __shfl_xor_sync(0xffffffffu, ss, o);
        float mu0 = __shfl_sync(0xffffffffu, m0, 0);
        float neg = 2.0f * mu0 * mu0 - ss;
        float inv = rsqrtf(fmaxf(neg, EPS_)) * (1.0f / H_);
        a0 += m0 * inv; a1 += m1 * inv; a2 += m2 * inv;
    }
    float ss = a0 * a0 + a1 * a1 + a2 * a2;
    #pragma unroll
    for (int o = 16; o; o >>= 1) ss += __shfl_xor_sync(0xffffffffu, ss, o);
    float av0 = __shfl_sync(0xffffffffu, a0, 0);
    float neg = 2.0f * av0 * av0 - ss;
    float inv2 = rsqrtf(fmaxf(neg, EPS_));
    float sp0 = a0 * inv2, sp1 = a1 * inv2, sp2 = a2 * inv2;

    float ssp = sp1 * sp1 + ((lane == 0) ? sp2 * sp2 : sp0 * sp0);
    #pragma unroll
    for (int o = 16; o; o >>= 1) ssp += __shfl_xor_sync(0xffffffffu, ssp, o);
    float t = sqrtf(1.0f + ssp);

    float* o_ = out + ((size_t)b * N_ + n) * AD_;
    o_[lane]      = (lane == 0) ? t : sp0;
    o_[lane + 32] = sp1;
    if (lane == 0) o_[64] = sp2;
}

// ---------------- launch ------------------------------------------------------
extern "C" void kernel_launch(void* const* d_in, const int* in_sizes, int n_in,
                              void* d_out, int out_size)
{
    const float* x     = (const float*)d_in[0];
    const float* Wq    = (const float*)d_in[1];
    const float* Wk    = (const float*)d_in[2];
    const float* Wv    = (const float*)d_in[3];
    const float* bq    = (const float*)d_in[4];
    const float* bk    = (const float*)d_in[5];
    const float* bv    = (const float*)d_in[6];
    const float* scale = (const float*)d_in[7];
    float* out = (float*)d_out;

    cudaFuncSetAttribute(proj_kernel, cudaFuncAttributeMaxDynamicSharedMemorySize, PROJ_SMEM);
    cudaFuncSetAttribute(attn_kernel, cudaFuncAttributeMaxDynamicSharedMemorySize, ATTN_SMEM);

    prep_kernel<<<1024, 256>>>(x, Wq, Wk, Wv);
    proj_kernel<<<dim3(N_/128, H_, B_), 256, PROJ_SMEM>>>(bq, bk, bv);
    attn_kernel<<<dim3(N_/128, BH_), 256, ATTN_SMEM>>>(scale);
    finalize_kernel<<<(B_*N_*32 + 255)/256, 256>>>(out);
}

// round 9
// speedup vs baseline: 1.0029x; 1.0029x over previous
#include <cuda_runtime.h>
#include <cuda_bf16.h>
#include <math.h>
#include <stdint.h>

#define B_   4
#define N_   2048
#define KD_  129
#define H_   8
#define DO_  64
#define AD_  65
#define BH_  (B_*H_)
#define EPS_ 1e-7f
#define MUP_ 68
#define KP_  144

// ---------------- scratch ----------------------------------------------------
__device__ __nv_bfloat16 g_Xb[B_*N_*KP_];
__device__ __nv_bfloat16 g_Wb[24*DO_*KP_];
__device__ __nv_bfloat16 g_Qb[BH_*N_*64];
__device__ __nv_bfloat16 g_Kb[BH_*N_*64];
__device__ float         g_Q0[BH_*N_];
__device__ float         g_KV0[BH_*N_*2];        // (k_time, v_time) fp32 pairs
__device__ __nv_bfloat16 g_Vt[BH_*64*N_];        // V^T spatial only [bh][64][N]
__device__ float         g_Mu[BH_*N_*MUP_];      // UNNORMALIZED midpoint accum

// ---------------- helpers ----------------------------------------------------
__device__ __forceinline__ uint32_t smem_u32(const void* p) {
    uint32_t a;
    asm("{ .reg .u64 t; cvta.to.shared.u64 t, %1; cvt.u32.u64 %0, t; }" : "=r"(a) : "l"(p));
    return a;
}
__device__ __forceinline__ void cpa16(uint32_t dst, const void* src) {
    asm volatile("cp.async.cg.shared.global [%0], [%1], 16;" :: "r"(dst), "l"(src));
}
#define CP_COMMIT() asm volatile("cp.async.commit_group;" ::: "memory")
#define CP_WAIT0()  asm volatile("cp.async.wait_group 0;" ::: "memory")
#define CP_WAIT1()  asm volatile("cp.async.wait_group 1;" ::: "memory")

__device__ __forceinline__ void mma16816(float* d,
    uint32_t a0, uint32_t a1, uint32_t a2, uint32_t a3,
    uint32_t b0, uint32_t b1)
{
    asm volatile("mma.sync.aligned.m16n8k16.row.col.f32.bf16.bf16.f32 "
        "{%0,%1,%2,%3}, {%4,%5,%6,%7}, {%8,%9}, {%0,%1,%2,%3};"
        : "+f"(d[0]), "+f"(d[1]), "+f"(d[2]), "+f"(d[3])
        : "r"(a0), "r"(a1), "r"(a2), "r"(a3), "r"(b0), "r"(b1));
}
__device__ __forceinline__ void ldm_x4(uint32_t& r0, uint32_t& r1,
                                       uint32_t& r2, uint32_t& r3, uint32_t a)
{
    asm volatile("ldmatrix.sync.aligned.m8n8.x4.shared.b16 {%0,%1,%2,%3}, [%4];"
        : "=r"(r0), "=r"(r1), "=r"(r2), "=r"(r3) : "r"(a));
}
__device__ __forceinline__ float ex2f(float x) {
    float r; asm("ex2.approx.ftz.f32 %0, %1;" : "=f"(r) : "f"(x)); return r;
}
__device__ __forceinline__ uint32_t bf2(float lo, float hi) {
    uint32_t r; asm("cvt.rn.bf16x2.f32 %0, %1, %2;" : "=r"(r) : "f"(hi), "f"(lo)); return r;
}

// ---------------- prep --------------------------------------------------------
__global__ __launch_bounds__(256) void prep_kernel(
    const float* __restrict__ x,
    const float* __restrict__ Wq, const float* __restrict__ Wk,
    const float* __restrict__ Wv)
{
    const int nt = gridDim.x * 256;
    const int t0 = blockIdx.x * 256 + threadIdx.x;

    for (int i = t0; i < B_*N_*KP_; i += nt) {
        int bn = i / KP_, c = i - bn * KP_;
        g_Xb[i] = __float2bfloat16_rn(c < KD_ ? x[(size_t)bn * KD_ + c] : 0.f);
    }
    for (int i = t0; i < 24*DO_*KP_; i += nt) {
        int idx = i / (DO_*KP_);
        int r   = i - idx * (DO_*KP_);
        int d   = r / KP_, k = r - d * KP_;
        int m = idx >> 3, h = idx & 7;
        const float* W = (m == 0 ? Wq : (m == 1 ? Wk : Wv)) + h * KD_ * DO_;
        g_Wb[i] = __float2bfloat16_rn(k < KD_ ? W[k * DO_ + d] : 0.f);
    }
}

// ---------------- projection v2 (round-8) -------------------------------------
#define PX_ST 76
#define PROJ_XS_B (128*PX_ST*4)
#define PROJ_W1_B (64*PX_ST*4)
#define PROJ_SMEM (PROJ_XS_B + 3*PROJ_W1_B)
#define TS_ST 136

__global__ __launch_bounds__(256, 2) void proj_kernel(
    const float* __restrict__ bq, const float* __restrict__ bk,
    const float* __restrict__ bv)
{
    extern __shared__ char smem[];
    const uint32_t sb = smem_u32(smem);
    const int tid = threadIdx.x, wid = tid >> 5, lane = tid & 31;
    const int n0 = blockIdx.x * 128;
    const int h  = blockIdx.y;
    const int b  = blockIdx.z;
    const int bh = b * H_ + h;

    const __nv_bfloat16* Xg = g_Xb + (size_t)b * N_ * KP_;

    for (int i = tid; i < 128 * 18; i += 256) {
        int r = i / 18, c = i - r * 18;
        cpa16(sb + r * 304 + c * 16, Xg + (size_t)(n0 + r) * KP_ + c * 8);
    }
    #pragma unroll
    for (int m = 0; m < 3; m++) {
        const __nv_bfloat16* Wg = g_Wb + (size_t)(m * 8 + h) * DO_ * KP_;
        for (int i = tid; i < 64 * 18; i += 256) {
            int r = i / 18, c = i - r * 18;
            cpa16(sb + PROJ_XS_B + m * PROJ_W1_B + r * 304 + c * 16,
                  Wg + (size_t)r * KP_ + c * 8);
        }
    }
    CP_COMMIT();
    CP_WAIT0();
    __syncthreads();

    const int r0 = wid * 16;
    const int lq = lane >> 2, lm = lane & 3;
    const uint32_t offA = (uint32_t)((lane & 7) + ((lane >> 3) & 1) * 8) * 304u
                        + ((lane >> 4) & 1) * 16u;
    const uint32_t offB = (uint32_t)((lane & 7) + ((lane >> 4) & 1) * 8) * 304u
                        + ((lane >> 3) & 1) * 16u;
    const uint32_t xa_base = sb + r0 * 304 + offA;

    #pragma unroll
    for (int m = 0; m < 3; m++) {
        const float* bias = (m == 0 ? bq : (m == 1 ? bk : bv)) + h * DO_;
        const uint32_t wb_base = sb + PROJ_XS_B + m * PROJ_W1_B + offB;

        float o[8][4];
        #pragma unroll
        for (int jt = 0; jt < 8; jt++) {
            float b0v = bias[jt * 8 + 2 * lm];
            float b1v = bias[jt * 8 + 2 * lm + 1];
            o[jt][0] = b0v; o[jt][1] = b1v; o[jt][2] = b0v; o[jt][3] = b1v;
        }

        #pragma unroll
        for (int ks = 0; ks < 9; ks++) {
            uint32_t a0, a1, a2, a3;
            ldm_x4(a0, a1, a2, a3, xa_base + ks * 32);
            #pragma unroll
            for (int p = 0; p < 4; p++) {
                uint32_t b0, b1, b2, b3;
                ldm_x4(b0, b1, b2, b3, wb_base + p * (16 * 304) + ks * 32);
                mma16816(o[2*p],   a0, a1, a2, a3, b0, b1);
                mma16816(o[2*p+1], a0, a1, a2, a3, b2, b3);
            }
        }

        float rs0 = 0.f, rs1 = 0.f;
        #pragma unroll
        for (int jt = 0; jt < 8; jt++) {
            rs0 += o[jt][0]*o[jt][0] + o[jt][1]*o[jt][1];
            rs1 += o[jt][2]*o[jt][2] + o[jt][3]*o[jt][3];
        }
        rs0 += __shfl_xor_sync(0xffffffffu, rs0, 1);
        rs0 += __shfl_xor_sync(0xffffffffu, rs0, 2);
        rs1 += __shfl_xor_sync(0xffffffffu, rs1, 1);
        rs1 += __shfl_xor_sync(0xffffffffu, rs1, 2);
        const float t0v = sqrtf(1.0f + rs0);
        const float t1v = sqrtf(1.0f + rs1);

        const int nA = n0 + r0 + lq, nB = nA + 8;

        if (m < 2) {
            __nv_bfloat16* gb = (m == 0 ? g_Qb : g_Kb) + (size_t)bh * N_ * 64;
            #pragma unroll
            for (int jt = 0; jt < 8; jt++) {
                *(uint32_t*)(gb + (size_t)nA * 64 + jt * 8 + 2 * lm) = bf2(o[jt][0], o[jt][1]);
                *(uint32_t*)(gb + (size_t)nB * 64 + jt * 8 + 2 * lm) = bf2(o[jt][2], o[jt][3]);
            }
            if (lm == 0) {
                if (m == 0) {
                    g_Q0[(size_t)bh * N_ + nA] = t0v;
                    g_Q0[(size_t)bh * N_ + nB] = t1v;
                } else {
                    g_KV0[((size_t)bh * N_ + nA) * 2] = t0v;
                    g_KV0[((size_t)bh * N_ + nB) * 2] = t1v;
                }
            }
        } else {
            __syncthreads();
            __nv_bfloat16* Ts = (__nv_bfloat16*)smem;
            const int rA = r0 + lq, rB = rA + 8;
            #pragma unroll
            for (int jt = 0; jt < 8; jt++) {
                int c0 = jt * 8 + 2 * lm;
                Ts[c0 * TS_ST + rA]       = __float2bfloat16_rn(o[jt][0]);
                Ts[(c0 + 1) * TS_ST + rA] = __float2bfloat16_rn(o[jt][1]);
                Ts[c0 * TS_ST + rB]       = __float2bfloat16_rn(o[jt][2]);
                Ts[(c0 + 1) * TS_ST + rB] = __float2bfloat16_rn(o[jt][3]);
            }
            if (lm == 0) {
                g_KV0[((size_t)bh * N_ + nA) * 2 + 1] = t0v;
                g_KV0[((size_t)bh * N_ + nB) * 2 + 1] = t1v;
            }
            __syncthreads();

            __nv_bfloat16* gv = g_Vt + (size_t)bh * 64 * N_;
            for (int i = tid; i < 64 * 16; i += 256) {
                int a = i >> 4, ch = i & 15;
                uint4 v = *(const uint4*)(Ts + a * TS_ST + ch * 8);
                *(uint4*)(gv + (size_t)a * N_ + n0 + ch * 8) = v;
            }
        }
    }
}

// ---------------- attention: PV pipelined one tile behind S -------------------
// 8 warps x (16 q-rows x 64 keys). 4-slot ring, distance-2 prefetch, occ 2.
// Softmax denominator dropped (Lorentz normalize is scale invariant).
#define OFF_Q    0
#define OFF_AQ0  18432
#define OFF_ST   18944
#define STG_V    9216
#define STG_KV0  18432
#define STG_SZ   18944
#define ATTN_SMEM (OFF_ST + 4*STG_SZ)

__global__ __launch_bounds__(256, 2) void attn_kernel(const float* __restrict__ scale_p)
{
    extern __shared__ char smem[];
    const uint32_t sb = smem_u32(smem);
    const int tid = threadIdx.x, wid = tid >> 5, lane = tid & 31;
    const int bh  = blockIdx.y;
    const int q0g = blockIdx.x * 128;

    const __nv_bfloat16* Qg = g_Qb + (size_t)bh * N_ * 64;
    const __nv_bfloat16* Kg = g_Kb + (size_t)bh * N_ * 64;
    const __nv_bfloat16* Vg = g_Vt + (size_t)bh * 64 * N_;
    const float* kv0 = g_KV0 + (size_t)bh * N_ * 2;

    const float a2c = 2.0f * 1.4426950408889634f / (scale_p[0] + EPS_);

    // prologue: group0 = Q + stage0, group1 = stage1
    for (int i = tid; i < 1024; i += 256) {
        int r = i >> 3, c = i & 7;
        cpa16(sb + OFF_Q + r * 144 + c * 16, Qg + (size_t)(q0g + r) * 64 + c * 8);
    }
    {
        const uint32_t stg = sb + OFF_ST;
        for (int i = tid; i < 512; i += 256) {
            int r = i >> 3, c = i & 7;
            cpa16(stg + r * 144 + c * 16, Kg + (size_t)r * 64 + c * 8);
        }
        for (int i = tid; i < 512; i += 256) {
            int a = i >> 3, c = i & 7;
            cpa16(stg + STG_V + a * 144 + c * 16, Vg + (size_t)a * N_ + c * 8);
        }
        if (tid < 32) cpa16(stg + STG_KV0 + tid * 16, kv0 + tid * 4);
        CP_COMMIT();
    }
    {
        const uint32_t stg = sb + OFF_ST + STG_SZ;
        for (int i = tid; i < 512; i += 256) {
            int r = i >> 3, c = i & 7;
            cpa16(stg + r * 144 + c * 16, Kg + (size_t)(64 + r) * 64 + c * 8);
        }
        for (int i = tid; i < 512; i += 256) {
            int a = i >> 3, c = i & 7;
            cpa16(stg + STG_V + a * 144 + c * 16, Vg + (size_t)a * N_ + 64 + c * 8);
        }
        if (tid < 32) cpa16(stg + STG_KV0 + tid * 16, kv0 + 128 + tid * 4);
        CP_COMMIT();
    }
    if (tid < 128)
        ((float*)(smem + OFF_AQ0))[tid] = a2c * g_Q0[(size_t)bh * N_ + q0g + tid];

    CP_WAIT1();          // Q + stage0 complete
    __syncthreads();

    const int r0 = wid * 16;
    const int lq = lane >> 2, lm = lane & 3;
    const uint32_t offl =
        (uint32_t)((((lane >> 3) & 2) ? 8 : 0) + (lane & 7)) * 144u
        + (((lane >> 3) & 1) ? 16u : 0u);

    uint32_t qf[4][4];
    {
        const uint32_t* QSw = (const uint32_t*)(smem + OFF_Q);
        #pragma unroll
        for (int ks = 0; ks < 4; ks++) {
            const int dw = ks * 8 + lm;
            qf[ks][0] = QSw[(r0 + lq) * 36 + dw];
            qf[ks][1] = QSw[(r0 + lq + 8) * 36 + dw];
            qf[ks][2] = QSw[(r0 + lq) * 36 + dw + 4];
            qf[ks][3] = QSw[(r0 + lq + 8) * 36 + dw + 4];
        }
    }
    const float aq0 = ((const float*)(smem + OFF_AQ0))[r0 + lq];
    const float aq1 = ((const float*)(smem + OFF_AQ0))[r0 + lq + 8];

    float o[8][4];
    #pragma unroll
    for (int at = 0; at < 8; at++)
        #pragma unroll
        for (int c = 0; c < 4; c++) o[at][c] = 0.f;
    float tac0 = 0.f, tac1 = 0.f;
    uint32_t pf[8][2];

    for (int t = 0; t < 32; t++) {
        if (t) { CP_WAIT1(); __syncthreads(); }
        const uint32_t stgo = OFF_ST + (t & 3) * STG_SZ;
        const uint32_t ks_base = sb + stgo + offl;
        // V of the PREVIOUS tile (slot (t-1)&3)
        const uint32_t vs_prev = sb + OFF_ST + ((t + 3) & 3) * STG_SZ + STG_V + offl;

        // S = Q.K^T for tile t
        float s[8][4];
        #pragma unroll
        for (int jt = 0; jt < 8; jt++)
            #pragma unroll
            for (int c = 0; c < 4; c++) s[jt][c] = 0.f;

        #pragma unroll
        for (int ks = 0; ks < 4; ks++) {
            #pragma unroll
            for (int q = 0; q < 4; q++) {
                uint32_t b0, b1, b2, b3;
                ldm_x4(b0, b1, b2, b3, ks_base + q * 2304 + ks * 32);
                mma16816(s[2*q],   qf[ks][0], qf[ks][1], qf[ks][2], qf[ks][3], b0, b1);
                mma16816(s[2*q+1], qf[ks][0], qf[ks][1], qf[ks][2], qf[ks][3], b2, b3);
            }
        }

        // O += P(t-1).V(t-1)  — independent of S(t); fills the softmax gap
        if (t) {
            #pragma unroll
            for (int kt = 0; kt < 4; kt++) {
                const uint32_t A0 = pf[2*kt][0], A1 = pf[2*kt][1];
                const uint32_t A2 = pf[2*kt+1][0], A3 = pf[2*kt+1][1];
                #pragma unroll
                for (int p = 0; p < 4; p++) {
                    uint32_t b0, b1, b2, b3;
                    ldm_x4(b0, b1, b2, b3, vs_prev + p * 2304 + kt * 32);
                    mma16816(o[2*p],   A0, A1, A2, A3, b0, b1);
                    mma16816(o[2*p+1], A0, A1, A2, A3, b2, b3);
                }
            }
        }

        // softmax(t): unnormalized p (denominator cancels in Lorentz normalize)
        const float2* kvs = (const float2*)(smem + stgo + STG_KV0);
        #pragma unroll
        for (int jt = 0; jt < 8; jt++) {
            const float2 kva = kvs[jt * 8 + 2 * lm];
            const float2 kvb = kvs[jt * 8 + 2 * lm + 1];
            float p0 = ex2f(fmaf(a2c, s[jt][0], -aq0 * kva.x));
            float p1 = ex2f(fmaf(a2c, s[jt][1], -aq0 * kvb.x));
            float p2 = ex2f(fmaf(a2c, s[jt][2], -aq1 * kva.x));
            float p3 = ex2f(fmaf(a2c, s[jt][3], -aq1 * kvb.x));
            tac0 = fmaf(p0, kva.y, fmaf(p1, kvb.y, tac0));
            tac1 = fmaf(p2, kva.y, fmaf(p3, kvb.y, tac1));
            pf[jt][0] = bf2(p0, p1);
            pf[jt][1] = bf2(p2, p3);
        }

        // distance-2 prefetch: tile t+2 into slot (t+2)&3 (disjoint from t, t-1)
        if (t + 2 < 32) {
            const int j0 = (t + 2) * 64;
            const uint32_t pstg = sb + OFF_ST + ((t + 2) & 3) * STG_SZ;
            for (int i = tid; i < 512; i += 256) {
                int r = i >> 3, c = i & 7;
                cpa16(pstg + r * 144 + c * 16, Kg + (size_t)(j0 + r) * 64 + c * 8);
            }
            for (int i = tid; i < 512; i += 256) {
                int a = i >> 3, c = i & 7;
                cpa16(pstg + STG_V + a * 144 + c * 16, Vg + (size_t)a * N_ + j0 + c * 8);
            }
            if (tid < 32) cpa16(pstg + STG_KV0 + tid * 16, kv0 + (size_t)j0 * 2 + tid * 4);
        }
        CP_COMMIT();
    }

    // final PV for tile 31 (V in slot 31&3 = 3)
    {
        const uint32_t vs_last = sb + OFF_ST + 3 * STG_SZ + STG_V + offl;
        #pragma unroll
        for (int kt = 0; kt < 4; kt++) {
            const uint32_t A0 = pf[2*kt][0], A1 = pf[2*kt][1];
            const uint32_t A2 = pf[2*kt+1][0], A3 = pf[2*kt+1][1];
            #pragma unroll
            for (int p = 0; p < 4; p++) {
                uint32_t b0, b1, b2, b3;
                ldm_x4(b0, b1, b2, b3, vs_last + p * 2304 + kt * 32);
                mma16816(o[2*p],   A0, A1, A2, A3, b0, b1);
                mma16816(o[2*p+1], A0, A1, A2, A3, b2, b3);
            }
        }
    }

    // quad-reduce time channel; write UNNORMALIZED mu
    tac0 += __shfl_xor_sync(0xffffffffu, tac0, 1);
    tac0 += __shfl_xor_sync(0xffffffffu, tac0, 2);
    tac1 += __shfl_xor_sync(0xffffffffu, tac1, 1);
    tac1 += __shfl_xor_sync(0xffffffffu, tac1, 2);

    float* mA = g_Mu + ((size_t)bh * N_ + q0g + r0 + lq) * MUP_;
    float* mB = mA + 8 * MUP_;
    #pragma unroll
    for (int at = 0; at < 8; at++) {
        const int c = at * 8 + 2 * lm;
        mA[c + 1] = o[at][0];  mA[c + 2] = o[at][1];
        mB[c + 1] = o[at][2];  mB[c + 2] = o[at][3];
    }
    if (lm == 0) { mA[0] = tac0; mB[0] = tac1; }
}

// ---------------- finalize (unchanged; normalize is scale-invariant) ----------
__global__ __launch_bounds__(256) void finalize_kernel(float* __restrict__ out)
{
    const int gw = (blockIdx.x * blockDim.x + threadIdx.x) >> 5;
    const int lane = threadIdx.x & 31;
    if (gw >= B_ * N_) return;
    const int b = gw >> 11, n = gw & (N_ - 1);

    float a0 = 0.f, a1 = 0.f, a2 = 0.f;
    for (int h = 0; h < H_; h++) {
        const float* mu = g_Mu + ((size_t)(b * H_ + h) * N_ + n) * MUP_;
        float m0 = mu[lane];
        float m1 = mu[lane + 32];
        float m2 = (lane == 0) ? mu[64] : 0.f;
        float ss = m0 * m0 + m1 * m1 + m2 * m2;
        #pragma unroll
        for (int o = 16; o; o >>= 1) ss += __shfl_xor_sync(0xffffffffu, ss, o);
        float mu0 = __shfl_sync(0xffffffffu, m0, 0);
        float neg = 2.0f * mu0 * mu0 - ss;
        float inv = rsqrtf(fmaxf(neg, EPS_)) * (1.0f / H_);
        a0 += m0 * inv; a1 += m1 * inv; a2 += m2 * inv;
    }
    float ss = a0 * a0 + a1 * a1 + a2 * a2;
    #pragma unroll
    for (int o = 16; o; o >>= 1) ss += __shfl_xor_sync(0xffffffffu, ss, o);
    float av0 = __shfl_sync(0xffffffffu, a0, 0);
    float neg = 2.0f * av0 * av0 - ss;
    float inv2 = rsqrtf(fmaxf(neg, EPS_));
    float sp0 = a0 * inv2, sp1 = a1 * inv2, sp2 = a2 * inv2;

    float ssp = sp1 * sp1 + ((lane == 0) ? sp2 * sp2 : sp0 * sp0);
    #pragma unroll
    for (int o = 16; o; o >>= 1) ssp += __shfl_xor_sync(0xffffffffu, ssp, o);
    float t = sqrtf(1.0f + ssp);

    float* o_ = out + ((size_t)b * N_ + n) * AD_;
    o_[lane]      = (lane == 0) ? t : sp0;
    o_[lane + 32] = sp1;
    if (lane == 0) o_[64] = sp2;
}

// ---------------- launch ------------------------------------------------------
extern "C" void kernel_launch(void* const* d_in, const int* in_sizes, int n_in,
                              void* d_out, int out_size)
{
    const float* x     = (const float*)d_in[0];
    const float* Wq    = (const float*)d_in[1];
    const float* Wk    = (const float*)d_in[2];
    const float* Wv    = (const float*)d_in[3];
    const float* bq    = (const float*)d_in[4];
    const float* bk    = (const float*)d_in[5];
    const float* bv    = (const float*)d_in[6];
    const float* scale = (const float*)d_in[7];
    float* out = (float*)d_out;

    cudaFuncSetAttribute(proj_kernel, cudaFuncAttributeMaxDynamicSharedMemorySize, PROJ_SMEM);
    cudaFuncSetAttribute(attn_kernel, cudaFuncAttributeMaxDynamicSharedMemorySize, ATTN_SMEM);

    prep_kernel<<<1024, 256>>>(x, Wq, Wk, Wv);
    proj_kernel<<<dim3(N_/128, H_, B_), 256, PROJ_SMEM>>>(bq, bk, bv);
    attn_kernel<<<dim3(N_/128, BH_), 256, ATTN_SMEM>>>(scale);
    finalize_kernel<<<(B_*N_*32 + 255)/256, 256>>>(out);
}

// round 10
// speedup vs baseline: 1.0583x; 1.0552x over previous
#include <cuda_runtime.h>
#include <cuda_fp16.h>
#include <math.h>
#include <stdint.h>

#define B_   4
#define N_   2048
#define KD_  129
#define H_   8
#define DO_  64
#define AD_  65
#define BH_  (B_*H_)
#define EPS_ 1e-7f
#define MUP_ 68
#define KP_  144

// ---------------- scratch (fp16 storage now) ----------------------------------
__device__ __half g_Xb[B_*N_*KP_];
__device__ __half g_Wb[24*DO_*KP_];
__device__ __half g_Qb[BH_*N_*64];
__device__ __half g_Kb[BH_*N_*64];
__device__ float  g_Q0[BH_*N_];
__device__ float  g_KV0[BH_*N_*2];        // (k_time, v_time) fp32 pairs
__device__ __half g_Vt[BH_*64*N_];        // V^T spatial only [bh][64][N]
__device__ float  g_Mu[BH_*N_*MUP_];      // UNNORMALIZED midpoint accum

// ---------------- helpers ----------------------------------------------------
__device__ __forceinline__ uint32_t smem_u32(const void* p) {
    uint32_t a;
    asm("{ .reg .u64 t; cvta.to.shared.u64 t, %1; cvt.u32.u64 %0, t; }" : "=r"(a) : "l"(p));
    return a;
}
__device__ __forceinline__ void cpa16(uint32_t dst, const void* src) {
    asm volatile("cp.async.cg.shared.global [%0], [%1], 16;" :: "r"(dst), "l"(src));
}
#define CP_COMMIT() asm volatile("cp.async.commit_group;" ::: "memory")
#define CP_WAIT0()  asm volatile("cp.async.wait_group 0;" ::: "memory")
#define CP_WAIT1()  asm volatile("cp.async.wait_group 1;" ::: "memory")

// fp16 inputs, fp32 accumulate (proj + PV)
__device__ __forceinline__ void mma16816_f32(float* d,
    uint32_t a0, uint32_t a1, uint32_t a2, uint32_t a3,
    uint32_t b0, uint32_t b1)
{
    asm volatile("mma.sync.aligned.m16n8k16.row.col.f32.f16.f16.f32 "
        "{%0,%1,%2,%3}, {%4,%5,%6,%7}, {%8,%9}, {%0,%1,%2,%3};"
        : "+f"(d[0]), "+f"(d[1]), "+f"(d[2]), "+f"(d[3])
        : "r"(a0), "r"(a1), "r"(a2), "r"(a3), "r"(b0), "r"(b1));
}
// fp16 inputs, fp16 accumulate (S GEMM — tests the double-rate path)
__device__ __forceinline__ void mma16816_h(uint32_t* d,
    uint32_t a0, uint32_t a1, uint32_t a2, uint32_t a3,
    uint32_t b0, uint32_t b1)
{
    asm volatile("mma.sync.aligned.m16n8k16.row.col.f16.f16.f16.f16 "
        "{%0,%1}, {%2,%3,%4,%5}, {%6,%7}, {%0,%1};"
        : "+r"(d[0]), "+r"(d[1])
        : "r"(a0), "r"(a1), "r"(a2), "r"(a3), "r"(b0), "r"(b1));
}
__device__ __forceinline__ void ldm_x4(uint32_t& r0, uint32_t& r1,
                                       uint32_t& r2, uint32_t& r3, uint32_t a)
{
    asm volatile("ldmatrix.sync.aligned.m8n8.x4.shared.b16 {%0,%1,%2,%3}, [%4];"
        : "=r"(r0), "=r"(r1), "=r"(r2), "=r"(r3) : "r"(a));
}
__device__ __forceinline__ float ex2f(float x) {
    float r; asm("ex2.approx.ftz.f32 %0, %1;" : "=f"(r) : "f"(x)); return r;
}
// pack 2 floats -> f16x2 (lo in lower half), mirrors proven bf2 convention
__device__ __forceinline__ uint32_t h2(float lo, float hi) {
    uint32_t r; asm("cvt.rn.f16x2.f32 %0, %1, %2;" : "=r"(r) : "f"(hi), "f"(lo)); return r;
}

// ---------------- prep --------------------------------------------------------
__global__ __launch_bounds__(256) void prep_kernel(
    const float* __restrict__ x,
    const float* __restrict__ Wq, const float* __restrict__ Wk,
    const float* __restrict__ Wv)
{
    const int nt = gridDim.x * 256;
    const int t0 = blockIdx.x * 256 + threadIdx.x;

    for (int i = t0; i < B_*N_*KP_; i += nt) {
        int bn = i / KP_, c = i - bn * KP_;
        g_Xb[i] = __float2half_rn(c < KD_ ? x[(size_t)bn * KD_ + c] : 0.f);
    }
    for (int i = t0; i < 24*DO_*KP_; i += nt) {
        int idx = i / (DO_*KP_);
        int r   = i - idx * (DO_*KP_);
        int d   = r / KP_, k = r - d * KP_;
        int m = idx >> 3, h = idx & 7;
        const float* W = (m == 0 ? Wq : (m == 1 ? Wk : Wv)) + h * KD_ * DO_;
        g_Wb[i] = __float2half_rn(k < KD_ ? W[k * DO_ + d] : 0.f);
    }
}

// ---------------- projection (round-8 structure, fp16 types) ------------------
#define PX_ST 76
#define PROJ_XS_B (128*PX_ST*4)
#define PROJ_W1_B (64*PX_ST*4)
#define PROJ_SMEM (PROJ_XS_B + 3*PROJ_W1_B)
#define TS_ST 136

__global__ __launch_bounds__(256, 2) void proj_kernel(
    const float* __restrict__ bq, const float* __restrict__ bk,
    const float* __restrict__ bv)
{
    extern __shared__ char smem[];
    const uint32_t sb = smem_u32(smem);
    const int tid = threadIdx.x, wid = tid >> 5, lane = tid & 31;
    const int n0 = blockIdx.x * 128;
    const int h  = blockIdx.y;
    const int b  = blockIdx.z;
    const int bh = b * H_ + h;

    const __half* Xg = g_Xb + (size_t)b * N_ * KP_;

    for (int i = tid; i < 128 * 18; i += 256) {
        int r = i / 18, c = i - r * 18;
        cpa16(sb + r * 304 + c * 16, Xg + (size_t)(n0 + r) * KP_ + c * 8);
    }
    #pragma unroll
    for (int m = 0; m < 3; m++) {
        const __half* Wg = g_Wb + (size_t)(m * 8 + h) * DO_ * KP_;
        for (int i = tid; i < 64 * 18; i += 256) {
            int r = i / 18, c = i - r * 18;
            cpa16(sb + PROJ_XS_B + m * PROJ_W1_B + r * 304 + c * 16,
                  Wg + (size_t)r * KP_ + c * 8);
        }
    }
    CP_COMMIT();
    CP_WAIT0();
    __syncthreads();

    const int r0 = wid * 16;
    const int lq = lane >> 2, lm = lane & 3;
    const uint32_t offA = (uint32_t)((lane & 7) + ((lane >> 3) & 1) * 8) * 304u
                        + ((lane >> 4) & 1) * 16u;
    const uint32_t offB = (uint32_t)((lane & 7) + ((lane >> 4) & 1) * 8) * 304u
                        + ((lane >> 3) & 1) * 16u;
    const uint32_t xa_base = sb + r0 * 304 + offA;

    #pragma unroll
    for (int m = 0; m < 3; m++) {
        const float* bias = (m == 0 ? bq : (m == 1 ? bk : bv)) + h * DO_;
        const uint32_t wb_base = sb + PROJ_XS_B + m * PROJ_W1_B + offB;

        float o[8][4];
        #pragma unroll
        for (int jt = 0; jt < 8; jt++) {
            float b0v = bias[jt * 8 + 2 * lm];
            float b1v = bias[jt * 8 + 2 * lm + 1];
            o[jt][0] = b0v; o[jt][1] = b1v; o[jt][2] = b0v; o[jt][3] = b1v;
        }

        #pragma unroll
        for (int ks = 0; ks < 9; ks++) {
            uint32_t a0, a1, a2, a3;
            ldm_x4(a0, a1, a2, a3, xa_base + ks * 32);
            #pragma unroll
            for (int p = 0; p < 4; p++) {
                uint32_t b0, b1, b2, b3;
                ldm_x4(b0, b1, b2, b3, wb_base + p * (16 * 304) + ks * 32);
                mma16816_f32(o[2*p],   a0, a1, a2, a3, b0, b1);
                mma16816_f32(o[2*p+1], a0, a1, a2, a3, b2, b3);
            }
        }

        float rs0 = 0.f, rs1 = 0.f;
        #pragma unroll
        for (int jt = 0; jt < 8; jt++) {
            rs0 += o[jt][0]*o[jt][0] + o[jt][1]*o[jt][1];
            rs1 += o[jt][2]*o[jt][2] + o[jt][3]*o[jt][3];
        }
        rs0 += __shfl_xor_sync(0xffffffffu, rs0, 1);
        rs0 += __shfl_xor_sync(0xffffffffu, rs0, 2);
        rs1 += __shfl_xor_sync(0xffffffffu, rs1, 1);
        rs1 += __shfl_xor_sync(0xffffffffu, rs1, 2);
        const float t0v = sqrtf(1.0f + rs0);
        const float t1v = sqrtf(1.0f + rs1);

        const int nA = n0 + r0 + lq, nB = nA + 8;

        if (m < 2) {
            __half* gb = (m == 0 ? g_Qb : g_Kb) + (size_t)bh * N_ * 64;
            #pragma unroll
            for (int jt = 0; jt < 8; jt++) {
                *(uint32_t*)(gb + (size_t)nA * 64 + jt * 8 + 2 * lm) = h2(o[jt][0], o[jt][1]);
                *(uint32_t*)(gb + (size_t)nB * 64 + jt * 8 + 2 * lm) = h2(o[jt][2], o[jt][3]);
            }
            if (lm == 0) {
                if (m == 0) {
                    g_Q0[(size_t)bh * N_ + nA] = t0v;
                    g_Q0[(size_t)bh * N_ + nB] = t1v;
                } else {
                    g_KV0[((size_t)bh * N_ + nA) * 2] = t0v;
                    g_KV0[((size_t)bh * N_ + nB) * 2] = t1v;
                }
            }
        } else {
            __syncthreads();
            __half* Ts = (__half*)smem;
            const int rA = r0 + lq, rB = rA + 8;
            #pragma unroll
            for (int jt = 0; jt < 8; jt++) {
                int c0 = jt * 8 + 2 * lm;
                Ts[c0 * TS_ST + rA]       = __float2half_rn(o[jt][0]);
                Ts[(c0 + 1) * TS_ST + rA] = __float2half_rn(o[jt][1]);
                Ts[c0 * TS_ST + rB]       = __float2half_rn(o[jt][2]);
                Ts[(c0 + 1) * TS_ST + rB] = __float2half_rn(o[jt][3]);
            }
            if (lm == 0) {
                g_KV0[((size_t)bh * N_ + nA) * 2 + 1] = t0v;
                g_KV0[((size_t)bh * N_ + nB) * 2 + 1] = t1v;
            }
            __syncthreads();

            __half* gv = g_Vt + (size_t)bh * 64 * N_;
            for (int i = tid; i < 64 * 16; i += 256) {
                int a = i >> 4, ch = i & 15;
                uint4 v = *(const uint4*)(Ts + a * TS_ST + ch * 8);
                *(uint4*)(gv + (size_t)a * N_ + n0 + ch * 8) = v;
            }
        }
    }
}

// ---------------- attention: fp16-acc S GEMM, fp32-acc PV ---------------------
#define OFF_Q    0
#define OFF_AQ0  18432
#define OFF_ST   18944
#define STG_V    9216
#define STG_KV0  18432
#define STG_SZ   18944
#define ATTN_SMEM (OFF_ST + 4*STG_SZ)

__global__ __launch_bounds__(256, 2) void attn_kernel(const float* __restrict__ scale_p)
{
    extern __shared__ char smem[];
    const uint32_t sb = smem_u32(smem);
    const int tid = threadIdx.x, wid = tid >> 5, lane = tid & 31;
    const int bh  = blockIdx.y;
    const int q0g = blockIdx.x * 128;

    const __half* Qg = g_Qb + (size_t)bh * N_ * 64;
    const __half* Kg = g_Kb + (size_t)bh * N_ * 64;
    const __half* Vg = g_Vt + (size_t)bh * 64 * N_;
    const float* kv0 = g_KV0 + (size_t)bh * N_ * 2;

    const float a2c = 2.0f * 1.4426950408889634f / (scale_p[0] + EPS_);

    for (int i = tid; i < 1024; i += 256) {
        int r = i >> 3, c = i & 7;
        cpa16(sb + OFF_Q + r * 144 + c * 16, Qg + (size_t)(q0g + r) * 64 + c * 8);
    }
    {
        const uint32_t stg = sb + OFF_ST;
        for (int i = tid; i < 512; i += 256) {
            int r = i >> 3, c = i & 7;
            cpa16(stg + r * 144 + c * 16, Kg + (size_t)r * 64 + c * 8);
        }
        for (int i = tid; i < 512; i += 256) {
            int a = i >> 3, c = i & 7;
            cpa16(stg + STG_V + a * 144 + c * 16, Vg + (size_t)a * N_ + c * 8);
        }
        if (tid < 32) cpa16(stg + STG_KV0 + tid * 16, kv0 + tid * 4);
        CP_COMMIT();
    }
    {
        const uint32_t stg = sb + OFF_ST + STG_SZ;
        for (int i = tid; i < 512; i += 256) {
            int r = i >> 3, c = i & 7;
            cpa16(stg + r * 144 + c * 16, Kg + (size_t)(64 + r) * 64 + c * 8);
        }
        for (int i = tid; i < 512; i += 256) {
            int a = i >> 3, c = i & 7;
            cpa16(stg + STG_V + a * 144 + c * 16, Vg + (size_t)a * N_ + 64 + c * 8);
        }
        if (tid < 32) cpa16(stg + STG_KV0 + tid * 16, kv0 + 128 + tid * 4);
        CP_COMMIT();
    }
    if (tid < 128)
        ((float*)(smem + OFF_AQ0))[tid] = a2c * g_Q0[(size_t)bh * N_ + q0g + tid];

    CP_WAIT1();
    __syncthreads();

    const int r0 = wid * 16;
    const int lq = lane >> 2, lm = lane & 3;
    const uint32_t offl =
        (uint32_t)((((lane >> 3) & 2) ? 8 : 0) + (lane & 7)) * 144u
        + (((lane >> 3) & 1) ? 16u : 0u);

    uint32_t qf[4][4];
    {
        const uint32_t* QSw = (const uint32_t*)(smem + OFF_Q);
        #pragma unroll
        for (int ks = 0; ks < 4; ks++) {
            const int dw = ks * 8 + lm;
            qf[ks][0] = QSw[(r0 + lq) * 36 + dw];
            qf[ks][1] = QSw[(r0 + lq + 8) * 36 + dw];
            qf[ks][2] = QSw[(r0 + lq) * 36 + dw + 4];
            qf[ks][3] = QSw[(r0 + lq + 8) * 36 + dw + 4];
        }
    }
    const float aq0 = ((const float*)(smem + OFF_AQ0))[r0 + lq];
    const float aq1 = ((const float*)(smem + OFF_AQ0))[r0 + lq + 8];

    float o[8][4];
    #pragma unroll
    for (int at = 0; at < 8; at++)
        #pragma unroll
        for (int c = 0; c < 4; c++) o[at][c] = 0.f;
    float tac0 = 0.f, tac1 = 0.f;
    uint32_t pf[8][2];

    for (int t = 0; t < 32; t++) {
        if (t) { CP_WAIT1(); __syncthreads(); }
        const uint32_t stgo = OFF_ST + (t & 3) * STG_SZ;
        const uint32_t ks_base = sb + stgo + offl;
        const uint32_t vs_prev = sb + OFF_ST + ((t + 3) & 3) * STG_SZ + STG_V + offl;

        // S = Q.K^T, fp16 accumulate (2 regs per 16x8 tile)
        uint32_t sh[8][2];
        #pragma unroll
        for (int jt = 0; jt < 8; jt++) { sh[jt][0] = 0u; sh[jt][1] = 0u; }

        #pragma unroll
        for (int ks = 0; ks < 4; ks++) {
            #pragma unroll
            for (int q = 0; q < 4; q++) {
                uint32_t b0, b1, b2, b3;
                ldm_x4(b0, b1, b2, b3, ks_base + q * 2304 + ks * 32);
                mma16816_h(sh[2*q],   qf[ks][0], qf[ks][1], qf[ks][2], qf[ks][3], b0, b1);
                mma16816_h(sh[2*q+1], qf[ks][0], qf[ks][1], qf[ks][2], qf[ks][3], b2, b3);
            }
        }

        // O += P(t-1).V(t-1)
        if (t) {
            #pragma unroll
            for (int kt = 0; kt < 4; kt++) {
                const uint32_t A0 = pf[2*kt][0], A1 = pf[2*kt][1];
                const uint32_t A2 = pf[2*kt+1][0], A3 = pf[2*kt+1][1];
                #pragma unroll
                for (int p = 0; p < 4; p++) {
                    uint32_t b0, b1, b2, b3;
                    ldm_x4(b0, b1, b2, b3, vs_prev + p * 2304 + kt * 32);
                    mma16816_f32(o[2*p],   A0, A1, A2, A3, b0, b1);
                    mma16816_f32(o[2*p+1], A0, A1, A2, A3, b2, b3);
                }
            }
        }

        // softmax(t): unpack f16 scores, unnormalized p
        const float2* kvs = (const float2*)(smem + stgo + STG_KV0);
        #pragma unroll
        for (int jt = 0; jt < 8; jt++) {
            const float2 kva = kvs[jt * 8 + 2 * lm];
            const float2 kvb = kvs[jt * 8 + 2 * lm + 1];
            float2 slo = __half22float2(*(__half2*)&sh[jt][0]);  // rows lq
            float2 shi = __half22float2(*(__half2*)&sh[jt][1]);  // rows lq+8
            float p0 = ex2f(fmaf(a2c, slo.x, -aq0 * kva.x));
            float p1 = ex2f(fmaf(a2c, slo.y, -aq0 * kvb.x));
            float p2 = ex2f(fmaf(a2c, shi.x, -aq1 * kva.x));
            float p3 = ex2f(fmaf(a2c, shi.y, -aq1 * kvb.x));
            tac0 = fmaf(p0, kva.y, fmaf(p1, kvb.y, tac0));
            tac1 = fmaf(p2, kva.y, fmaf(p3, kvb.y, tac1));
            pf[jt][0] = h2(p0, p1);
            pf[jt][1] = h2(p2, p3);
        }

        if (t + 2 < 32) {
            const int j0 = (t + 2) * 64;
            const uint32_t pstg = sb + OFF_ST + ((t + 2) & 3) * STG_SZ;
            for (int i = tid; i < 512; i += 256) {
                int r = i >> 3, c = i & 7;
                cpa16(pstg + r * 144 + c * 16, Kg + (size_t)(j0 + r) * 64 + c * 8);
            }
            for (int i = tid; i < 512; i += 256) {
                int a = i >> 3, c = i & 7;
                cpa16(pstg + STG_V + a * 144 + c * 16, Vg + (size_t)a * N_ + j0 + c * 8);
            }
            if (tid < 32) cpa16(pstg + STG_KV0 + tid * 16, kv0 + (size_t)j0 * 2 + tid * 4);
        }
        CP_COMMIT();
    }

    // final PV (tile 31, V in slot 3)
    {
        const uint32_t vs_last = sb + OFF_ST + 3 * STG_SZ + STG_V + offl;
        #pragma unroll
        for (int kt = 0; kt < 4; kt++) {
            const uint32_t A0 = pf[2*kt][0], A1 = pf[2*kt][1];
            const uint32_t A2 = pf[2*kt+1][0], A3 = pf[2*kt+1][1];
            #pragma unroll
            for (int p = 0; p < 4; p++) {
                uint32_t b0, b1, b2, b3;
                ldm_x4(b0, b1, b2, b3, vs_last + p * 2304 + kt * 32);
                mma16816_f32(o[2*p],   A0, A1, A2, A3, b0, b1);
                mma16816_f32(o[2*p+1], A0, A1, A2, A3, b2, b3);
            }
        }
    }

    tac0 += __shfl_xor_sync(0xffffffffu, tac0, 1);
    tac0 += __shfl_xor_sync(0xffffffffu, tac0, 2);
    tac1 += __shfl_xor_sync(0xffffffffu, tac1, 1);
    tac1 += __shfl_xor_sync(0xffffffffu, tac1, 2);

    float* mA = g_Mu + ((size_t)bh * N_ + q0g + r0 + lq) * MUP_;
    float* mB = mA + 8 * MUP_;
    #pragma unroll
    for (int at = 0; at < 8; at++) {
        const int c = at * 8 + 2 * lm;
        mA[c + 1] = o[at][0];  mA[c + 2] = o[at][1];
        mB[c + 1] = o[at][2];  mB[c + 2] = o[at][3];
    }
    if (lm == 0) { mA[0] = tac0; mB[0] = tac1; }
}

// ---------------- finalize: ILP across heads ----------------------------------
__global__ __launch_bounds__(256) void finalize_kernel(float* __restrict__ out)
{
    const int gw = (blockIdx.x * blockDim.x + threadIdx.x) >> 5;
    const int lane = threadIdx.x & 31;
    if (gw >= B_ * N_) return;
    const int b = gw >> 11, n = gw & (N_ - 1);

    // load all 8 heads first (independent LDGs), then interleaved reductions
    float m0[H_], m1[H_], m2[H_], ssv[H_];
    #pragma unroll
    for (int h = 0; h < H_; h++) {
        const float* mu = g_Mu + ((size_t)(b * H_ + h) * N_ + n) * MUP_;
        m0[h] = mu[lane];
        m1[h] = mu[lane + 32];
        m2[h] = (lane == 0) ? mu[64] : 0.f;
        ssv[h] = m0[h]*m0[h] + m1[h]*m1[h] + m2[h]*m2[h];
    }
    #pragma unroll
    for (int o = 16; o; o >>= 1) {
        #pragma unroll
        for (int h = 0; h < H_; h++)
            ssv[h] += __shfl_xor_sync(0xffffffffu, ssv[h], o);
    }
    float mu0[H_];
    #pragma unroll
    for (int h = 0; h < H_; h++)
        mu0[h] = __shfl_sync(0xffffffffu, m0[h], 0);

    float a0 = 0.f, a1 = 0.f, a2 = 0.f;
    #pragma unroll
    for (int h = 0; h < H_; h++) {
        float neg = 2.0f * mu0[h] * mu0[h] - ssv[h];
        float inv = rsqrtf(fmaxf(neg, EPS_));
        a0 += m0[h] * inv; a1 += m1[h] * inv; a2 += m2[h] * inv;
    }
    float ss = a0 * a0 + a1 * a1 + a2 * a2;
    #pragma unroll
    for (int o = 16; o; o >>= 1) ss += __shfl_xor_sync(0xffffffffu, ss, o);
    float av0 = __shfl_sync(0xffffffffu, a0, 0);
    float neg = 2.0f * av0 * av0 - ss;
    float inv2 = rsqrtf(fmaxf(neg, EPS_));
    float sp0 = a0 * inv2, sp1 = a1 * inv2, sp2 = a2 * inv2;

    float ssp = sp1 * sp1 + ((lane == 0) ? sp2 * sp2 : sp0 * sp0);
    #pragma unroll
    for (int o = 16; o; o >>= 1) ssp += __shfl_xor_sync(0xffffffffu, ssp, o);
    float t = sqrtf(1.0f + ssp);

    float* o_ = out + ((size_t)b * N_ + n) * AD_;
    o_[lane]      = (lane == 0) ? t : sp0;
    o_[lane + 32] = sp1;
    if (lane == 0) o_[64] = sp2;
}

// ---------------- launch ------------------------------------------------------
extern "C" void kernel_launch(void* const* d_in, const int* in_sizes, int n_in,
                              void* d_out, int out_size)
{
    const float* x     = (const float*)d_in[0];
    const float* Wq    = (const float*)d_in[1];
    const float* Wk    = (const float*)d_in[2];
    const float* Wv    = (const float*)d_in[3];
    const float* bq    = (const float*)d_in[4];
    const float* bk    = (const float*)d_in[5];
    const float* bv    = (const float*)d_in[6];
    const float* scale = (const float*)d_in[7];
    float* out = (float*)d_out;

    cudaFuncSetAttribute(proj_kernel, cudaFuncAttributeMaxDynamicSharedMemorySize, PROJ_SMEM);
    cudaFuncSetAttribute(attn_kernel, cudaFuncAttributeMaxDynamicSharedMemorySize, ATTN_SMEM);

    prep_kernel<<<1024, 256>>>(x, Wq, Wk, Wv);
    proj_kernel<<<dim3(N_/128, H_, B_), 256, PROJ_SMEM>>>(bq, bk, bv);
    attn_kernel<<<dim3(N_/128, BH_), 256, ATTN_SMEM>>>(scale);
    finalize_kernel<<<(B_*N_*32 + 255)/256, 256>>>(out);
}

// round 11
// speedup vs baseline: 1.1084x; 1.0474x over previous
#include <cuda_runtime.h>
#include <cuda_fp16.h>
#include <math.h>
#include <stdint.h>

#define B_   4
#define N_   2048
#define KD_  129
#define H_   8
#define DO_  64
#define AD_  65
#define BH_  (B_*H_)
#define EPS_ 1e-7f
#define MUP_ 66       // fp16 mu row: spatial 0..63, time at 64, pad to 66
#define KP_  144

// ---------------- scratch ----------------------------------------------------
__device__ __half g_Xb[B_*N_*KP_];
__device__ __half g_Wb[24*DO_*KP_];
__device__ __half g_Qb[BH_*N_*64];
__device__ __half g_Kb[BH_*N_*64];
__device__ float  g_Q0[BH_*N_];
__device__ float  g_KV0[BH_*N_*2];        // (k_time, v_time) fp32 pairs
__device__ __half g_Vt[BH_*64*N_];        // V^T spatial only [bh][64][N]
__device__ __half g_Muh[2*BH_*N_*MUP_];   // partial (per key-half) mu, fp16

// ---------------- helpers ----------------------------------------------------
__device__ __forceinline__ uint32_t smem_u32(const void* p) {
    uint32_t a;
    asm("{ .reg .u64 t; cvta.to.shared.u64 t, %1; cvt.u32.u64 %0, t; }" : "=r"(a) : "l"(p));
    return a;
}
__device__ __forceinline__ void cpa16(uint32_t dst, const void* src) {
    asm volatile("cp.async.cg.shared.global [%0], [%1], 16;" :: "r"(dst), "l"(src));
}
#define CP_COMMIT() asm volatile("cp.async.commit_group;" ::: "memory")
#define CP_WAIT0()  asm volatile("cp.async.wait_group 0;" ::: "memory")
#define CP_WAIT1()  asm volatile("cp.async.wait_group 1;" ::: "memory")
#define CP_WAIT2()  asm volatile("cp.async.wait_group 2;" ::: "memory")

__device__ __forceinline__ void mma16816_f32(float* d,
    uint32_t a0, uint32_t a1, uint32_t a2, uint32_t a3,
    uint32_t b0, uint32_t b1)
{
    asm volatile("mma.sync.aligned.m16n8k16.row.col.f32.f16.f16.f32 "
        "{%0,%1,%2,%3}, {%4,%5,%6,%7}, {%8,%9}, {%0,%1,%2,%3};"
        : "+f"(d[0]), "+f"(d[1]), "+f"(d[2]), "+f"(d[3])
        : "r"(a0), "r"(a1), "r"(a2), "r"(a3), "r"(b0), "r"(b1));
}
__device__ __forceinline__ void mma16816_h(uint32_t* d,
    uint32_t a0, uint32_t a1, uint32_t a2, uint32_t a3,
    uint32_t b0, uint32_t b1)
{
    asm volatile("mma.sync.aligned.m16n8k16.row.col.f16.f16.f16.f16 "
        "{%0,%1}, {%2,%3,%4,%5}, {%6,%7}, {%0,%1};"
        : "+r"(d[0]), "+r"(d[1])
        : "r"(a0), "r"(a1), "r"(a2), "r"(a3), "r"(b0), "r"(b1));
}
__device__ __forceinline__ void ldm_x4(uint32_t& r0, uint32_t& r1,
                                       uint32_t& r2, uint32_t& r3, uint32_t a)
{
    asm volatile("ldmatrix.sync.aligned.m8n8.x4.shared.b16 {%0,%1,%2,%3}, [%4];"
        : "=r"(r0), "=r"(r1), "=r"(r2), "=r"(r3) : "r"(a));
}
__device__ __forceinline__ float ex2f(float x) {
    float r; asm("ex2.approx.ftz.f32 %0, %1;" : "=f"(r) : "f"(x)); return r;
}
__device__ __forceinline__ uint32_t h2(float lo, float hi) {
    uint32_t r; asm("cvt.rn.f16x2.f32 %0, %1, %2;" : "=r"(r) : "f"(hi), "f"(lo)); return r;
}

// ---------------- prep --------------------------------------------------------
__global__ __launch_bounds__(256) void prep_kernel(
    const float* __restrict__ x,
    const float* __restrict__ Wq, const float* __restrict__ Wk,
    const float* __restrict__ Wv)
{
    const int nt = gridDim.x * 256;
    const int t0 = blockIdx.x * 256 + threadIdx.x;

    for (int i = t0; i < B_*N_*KP_; i += nt) {
        int bn = i / KP_, c = i - bn * KP_;
        g_Xb[i] = __float2half_rn(c < KD_ ? x[(size_t)bn * KD_ + c] : 0.f);
    }
    for (int i = t0; i < 24*DO_*KP_; i += nt) {
        int idx = i / (DO_*KP_);
        int r   = i - idx * (DO_*KP_);
        int d   = r / KP_, k = r - d * KP_;
        int m = idx >> 3, h = idx & 7;
        const float* W = (m == 0 ? Wq : (m == 1 ? Wk : Wv)) + h * KD_ * DO_;
        g_Wb[i] = __float2half_rn(k < KD_ ? W[k * DO_ + d] : 0.f);
    }
}

// ---------------- projection (staged W waits) ---------------------------------
#define PX_ST 76
#define PROJ_XS_B (128*PX_ST*4)
#define PROJ_W1_B (64*PX_ST*4)
#define PROJ_SMEM (PROJ_XS_B + 3*PROJ_W1_B)
#define TS_ST 136

__global__ __launch_bounds__(256, 2) void proj_kernel(
    const float* __restrict__ bq, const float* __restrict__ bk,
    const float* __restrict__ bv)
{
    extern __shared__ char smem[];
    const uint32_t sb = smem_u32(smem);
    const int tid = threadIdx.x, wid = tid >> 5, lane = tid & 31;
    const int n0 = blockIdx.x * 128;
    const int h  = blockIdx.y;
    const int b  = blockIdx.z;
    const int bh = b * H_ + h;

    const __half* Xg = g_Xb + (size_t)b * N_ * KP_;

    // group0 = X + W0, group1 = W1, group2 = W2
    for (int i = tid; i < 128 * 18; i += 256) {
        int r = i / 18, c = i - r * 18;
        cpa16(sb + r * 304 + c * 16, Xg + (size_t)(n0 + r) * KP_ + c * 8);
    }
    {
        const __half* Wg = g_Wb + (size_t)h * DO_ * KP_;
        for (int i = tid; i < 64 * 18; i += 256) {
            int r = i / 18, c = i - r * 18;
            cpa16(sb + PROJ_XS_B + r * 304 + c * 16, Wg + (size_t)r * KP_ + c * 8);
        }
    }
    CP_COMMIT();
    #pragma unroll
    for (int m = 1; m < 3; m++) {
        const __half* Wg = g_Wb + (size_t)(m * 8 + h) * DO_ * KP_;
        for (int i = tid; i < 64 * 18; i += 256) {
            int r = i / 18, c = i - r * 18;
            cpa16(sb + PROJ_XS_B + m * PROJ_W1_B + r * 304 + c * 16,
                  Wg + (size_t)r * KP_ + c * 8);
        }
        CP_COMMIT();
    }

    const int r0 = wid * 16;
    const int lq = lane >> 2, lm = lane & 3;
    const uint32_t offA = (uint32_t)((lane & 7) + ((lane >> 3) & 1) * 8) * 304u
                        + ((lane >> 4) & 1) * 16u;
    const uint32_t offB = (uint32_t)((lane & 7) + ((lane >> 4) & 1) * 8) * 304u
                        + ((lane >> 3) & 1) * 16u;
    const uint32_t xa_base = sb + r0 * 304 + offA;

    #pragma unroll
    for (int m = 0; m < 3; m++) {
        if (m == 0) CP_WAIT2(); else if (m == 1) CP_WAIT1(); else CP_WAIT0();
        __syncthreads();

        const float* bias = (m == 0 ? bq : (m == 1 ? bk : bv)) + h * DO_;
        const uint32_t wb_base = sb + PROJ_XS_B + m * PROJ_W1_B + offB;

        float o[8][4];
        #pragma unroll
        for (int jt = 0; jt < 8; jt++) {
            float b0v = bias[jt * 8 + 2 * lm];
            float b1v = bias[jt * 8 + 2 * lm + 1];
            o[jt][0] = b0v; o[jt][1] = b1v; o[jt][2] = b0v; o[jt][3] = b1v;
        }

        #pragma unroll
        for (int ks = 0; ks < 9; ks++) {
            uint32_t a0, a1, a2, a3;
            ldm_x4(a0, a1, a2, a3, xa_base + ks * 32);
            #pragma unroll
            for (int p = 0; p < 4; p++) {
                uint32_t b0, b1, b2, b3;
                ldm_x4(b0, b1, b2, b3, wb_base + p * (16 * 304) + ks * 32);
                mma16816_f32(o[2*p],   a0, a1, a2, a3, b0, b1);
                mma16816_f32(o[2*p+1], a0, a1, a2, a3, b2, b3);
            }
        }

        float rs0 = 0.f, rs1 = 0.f;
        #pragma unroll
        for (int jt = 0; jt < 8; jt++) {
            rs0 += o[jt][0]*o[jt][0] + o[jt][1]*o[jt][1];
            rs1 += o[jt][2]*o[jt][2] + o[jt][3]*o[jt][3];
        }
        rs0 += __shfl_xor_sync(0xffffffffu, rs0, 1);
        rs0 += __shfl_xor_sync(0xffffffffu, rs0, 2);
        rs1 += __shfl_xor_sync(0xffffffffu, rs1, 1);
        rs1 += __shfl_xor_sync(0xffffffffu, rs1, 2);
        const float t0v = sqrtf(1.0f + rs0);
        const float t1v = sqrtf(1.0f + rs1);

        const int nA = n0 + r0 + lq, nB = nA + 8;

        if (m < 2) {
            __half* gb = (m == 0 ? g_Qb : g_Kb) + (size_t)bh * N_ * 64;
            #pragma unroll
            for (int jt = 0; jt < 8; jt++) {
                *(uint32_t*)(gb + (size_t)nA * 64 + jt * 8 + 2 * lm) = h2(o[jt][0], o[jt][1]);
                *(uint32_t*)(gb + (size_t)nB * 64 + jt * 8 + 2 * lm) = h2(o[jt][2], o[jt][3]);
            }
            if (lm == 0) {
                if (m == 0) {
                    g_Q0[(size_t)bh * N_ + nA] = t0v;
                    g_Q0[(size_t)bh * N_ + nB] = t1v;
                } else {
                    g_KV0[((size_t)bh * N_ + nA) * 2] = t0v;
                    g_KV0[((size_t)bh * N_ + nB) * 2] = t1v;
                }
            }
        } else {
            __syncthreads();
            __half* Ts = (__half*)smem;
            const int rA = r0 + lq, rB = rA + 8;
            #pragma unroll
            for (int jt = 0; jt < 8; jt++) {
                int c0 = jt * 8 + 2 * lm;
                Ts[c0 * TS_ST + rA]       = __float2half_rn(o[jt][0]);
                Ts[(c0 + 1) * TS_ST + rA] = __float2half_rn(o[jt][1]);
                Ts[c0 * TS_ST + rB]       = __float2half_rn(o[jt][2]);
                Ts[(c0 + 1) * TS_ST + rB] = __float2half_rn(o[jt][3]);
            }
            if (lm == 0) {
                g_KV0[((size_t)bh * N_ + nA) * 2 + 1] = t0v;
                g_KV0[((size_t)bh * N_ + nB) * 2 + 1] = t1v;
            }
            __syncthreads();

            __half* gv = g_Vt + (size_t)bh * 64 * N_;
            for (int i = tid; i < 64 * 16; i += 256) {
                int a = i >> 4, ch = i & 15;
                uint4 v = *(const uint4*)(Ts + a * TS_ST + ch * 8);
                *(uint4*)(gv + (size_t)a * N_ + n0 + ch * 8) = v;
            }
        }
    }
}

// ---------------- attention: key-split halves (tail reduction) ----------------
#define OFF_Q    0
#define OFF_AQ0  18432
#define OFF_ST   18944
#define STG_V    9216
#define STG_KV0  18432
#define STG_SZ   18944
#define ATTN_SMEM (OFF_ST + 4*STG_SZ)
#define NT_ 16   // key tiles per CTA (half of 32)

__global__ __launch_bounds__(256, 2) void attn_kernel(const float* __restrict__ scale_p)
{
    extern __shared__ char smem[];
    const uint32_t sb = smem_u32(smem);
    const int tid = threadIdx.x, wid = tid >> 5, lane = tid & 31;
    const int bh  = blockIdx.y;
    const int q0g = blockIdx.x * 128;
    const int z   = blockIdx.z;          // key half
    const int kb  = z * 1024;

    const __half* Qg = g_Qb + (size_t)bh * N_ * 64;
    const __half* Kg = g_Kb + (size_t)bh * N_ * 64;
    const __half* Vg = g_Vt + (size_t)bh * 64 * N_;
    const float* kv0 = g_KV0 + (size_t)bh * N_ * 2;

    const float a2c = 2.0f * 1.4426950408889634f / (scale_p[0] + EPS_);

    for (int i = tid; i < 1024; i += 256) {
        int r = i >> 3, c = i & 7;
        cpa16(sb + OFF_Q + r * 144 + c * 16, Qg + (size_t)(q0g + r) * 64 + c * 8);
    }
    #pragma unroll
    for (int st = 0; st < 2; st++) {
        const int j0 = kb + st * 64;
        const uint32_t stg = sb + OFF_ST + st * STG_SZ;
        for (int i = tid; i < 512; i += 256) {
            int r = i >> 3, c = i & 7;
            cpa16(stg + r * 144 + c * 16, Kg + (size_t)(j0 + r) * 64 + c * 8);
        }
        for (int i = tid; i < 512; i += 256) {
            int a = i >> 3, c = i & 7;
            cpa16(stg + STG_V + a * 144 + c * 16, Vg + (size_t)a * N_ + j0 + c * 8);
        }
        if (tid < 32) cpa16(stg + STG_KV0 + tid * 16, kv0 + (size_t)j0 * 2 + tid * 4);
        CP_COMMIT();
    }
    if (tid < 128)
        ((float*)(smem + OFF_AQ0))[tid] = a2c * g_Q0[(size_t)bh * N_ + q0g + tid];

    CP_WAIT1();
    __syncthreads();

    const int r0 = wid * 16;
    const int lq = lane >> 2, lm = lane & 3;
    const uint32_t offl =
        (uint32_t)((((lane >> 3) & 2) ? 8 : 0) + (lane & 7)) * 144u
        + (((lane >> 3) & 1) ? 16u : 0u);

    uint32_t qf[4][4];
    {
        const uint32_t* QSw = (const uint32_t*)(smem + OFF_Q);
        #pragma unroll
        for (int ks = 0; ks < 4; ks++) {
            const int dw = ks * 8 + lm;
            qf[ks][0] = QSw[(r0 + lq) * 36 + dw];
            qf[ks][1] = QSw[(r0 + lq + 8) * 36 + dw];
            qf[ks][2] = QSw[(r0 + lq) * 36 + dw + 4];
            qf[ks][3] = QSw[(r0 + lq + 8) * 36 + dw + 4];
        }
    }
    const float aq0 = ((const float*)(smem + OFF_AQ0))[r0 + lq];
    const float aq1 = ((const float*)(smem + OFF_AQ0))[r0 + lq + 8];

    float o[8][4];
    #pragma unroll
    for (int at = 0; at < 8; at++)
        #pragma unroll
        for (int c = 0; c < 4; c++) o[at][c] = 0.f;
    float tac0 = 0.f, tac1 = 0.f;
    uint32_t pf[8][2];

    for (int t = 0; t < NT_; t++) {
        if (t) { CP_WAIT1(); __syncthreads(); }
        const uint32_t stgo = OFF_ST + (t & 3) * STG_SZ;
        const uint32_t ks_base = sb + stgo + offl;
        const uint32_t vs_prev = sb + OFF_ST + ((t + 3) & 3) * STG_SZ + STG_V + offl;

        uint32_t sh[8][2];
        #pragma unroll
        for (int jt = 0; jt < 8; jt++) { sh[jt][0] = 0u; sh[jt][1] = 0u; }

        #pragma unroll
        for (int ks = 0; ks < 4; ks++) {
            #pragma unroll
            for (int q = 0; q < 4; q++) {
                uint32_t b0, b1, b2, b3;
                ldm_x4(b0, b1, b2, b3, ks_base + q * 2304 + ks * 32);
                mma16816_h(sh[2*q],   qf[ks][0], qf[ks][1], qf[ks][2], qf[ks][3], b0, b1);
                mma16816_h(sh[2*q+1], qf[ks][0], qf[ks][1], qf[ks][2], qf[ks][3], b2, b3);
            }
        }

        if (t) {
            #pragma unroll
            for (int kt = 0; kt < 4; kt++) {
                const uint32_t A0 = pf[2*kt][0], A1 = pf[2*kt][1];
                const uint32_t A2 = pf[2*kt+1][0], A3 = pf[2*kt+1][1];
                #pragma unroll
                for (int p = 0; p < 4; p++) {
                    uint32_t b0, b1, b2, b3;
                    ldm_x4(b0, b1, b2, b3, vs_prev + p * 2304 + kt * 32);
                    mma16816_f32(o[2*p],   A0, A1, A2, A3, b0, b1);
                    mma16816_f32(o[2*p+1], A0, A1, A2, A3, b2, b3);
                }
            }
        }

        const float2* kvs = (const float2*)(smem + stgo + STG_KV0);
        #pragma unroll
        for (int jt = 0; jt < 8; jt++) {
            const float2 kva = kvs[jt * 8 + 2 * lm];
            const float2 kvb = kvs[jt * 8 + 2 * lm + 1];
            float2 slo = __half22float2(*(__half2*)&sh[jt][0]);
            float2 shi = __half22float2(*(__half2*)&sh[jt][1]);
            float p0 = ex2f(fmaf(a2c, slo.x, -aq0 * kva.x));
            float p1 = ex2f(fmaf(a2c, slo.y, -aq0 * kvb.x));
            float p2 = ex2f(fmaf(a2c, shi.x, -aq1 * kva.x));
            float p3 = ex2f(fmaf(a2c, shi.y, -aq1 * kvb.x));
            tac0 = fmaf(p0, kva.y, fmaf(p1, kvb.y, tac0));
            tac1 = fmaf(p2, kva.y, fmaf(p3, kvb.y, tac1));
            pf[jt][0] = h2(p0, p1);
            pf[jt][1] = h2(p2, p3);
        }

        if (t + 2 < NT_) {
            const int j0 = kb + (t + 2) * 64;
            const uint32_t pstg = sb + OFF_ST + ((t + 2) & 3) * STG_SZ;
            for (int i = tid; i < 512; i += 256) {
                int r = i >> 3, c = i & 7;
                cpa16(pstg + r * 144 + c * 16, Kg + (size_t)(j0 + r) * 64 + c * 8);
            }
            for (int i = tid; i < 512; i += 256) {
                int a = i >> 3, c = i & 7;
                cpa16(pstg + STG_V + a * 144 + c * 16, Vg + (size_t)a * N_ + j0 + c * 8);
            }
            if (tid < 32) cpa16(pstg + STG_KV0 + tid * 16, kv0 + (size_t)j0 * 2 + tid * 4);
        }
        CP_COMMIT();
    }

    // final PV (tile NT_-1 = 15, V in slot 15&3 = 3)
    {
        const uint32_t vs_last = sb + OFF_ST + 3 * STG_SZ + STG_V + offl;
        #pragma unroll
        for (int kt = 0; kt < 4; kt++) {
            const uint32_t A0 = pf[2*kt][0], A1 = pf[2*kt][1];
            const uint32_t A2 = pf[2*kt+1][0], A3 = pf[2*kt+1][1];
            #pragma unroll
            for (int p = 0; p < 4; p++) {
                uint32_t b0, b1, b2, b3;
                ldm_x4(b0, b1, b2, b3, vs_last + p * 2304 + kt * 32);
                mma16816_f32(o[2*p],   A0, A1, A2, A3, b0, b1);
                mma16816_f32(o[2*p+1], A0, A1, A2, A3, b2, b3);
            }
        }
    }

    tac0 += __shfl_xor_sync(0xffffffffu, tac0, 1);
    tac0 += __shfl_xor_sync(0xffffffffu, tac0, 2);
    tac1 += __shfl_xor_sync(0xffffffffu, tac1, 1);
    tac1 += __shfl_xor_sync(0xffffffffu, tac1, 2);

    // write partial mu (fp16): spatial at [c], time at [64]
    __half* mA = g_Muh + ((size_t)(z * BH_ + bh) * N_ + q0g + r0 + lq) * MUP_;
    __half* mB = mA + 8 * MUP_;
    #pragma unroll
    for (int at = 0; at < 8; at++) {
        const int c = at * 8 + 2 * lm;        // even -> aligned __half2
        *(uint32_t*)(mA + c) = h2(o[at][0], o[at][1]);
        *(uint32_t*)(mB + c) = h2(o[at][2], o[at][3]);
    }
    if (lm == 0) { mA[64] = __float2half_rn(tac0); mB[64] = __float2half_rn(tac1); }
}

// ---------------- finalize: sum halves, batched reductions --------------------
__global__ __launch_bounds__(256) void finalize_kernel(float* __restrict__ out)
{
    const int gw = (blockIdx.x * blockDim.x + threadIdx.x) >> 5;
    const int lane = threadIdx.x & 31;
    if (gw >= B_ * N_) return;
    const int b = gw >> 11, n = gw & (N_ - 1);

    float mx[H_], my[H_], tv[H_], ssv[H_];
    #pragma unroll
    for (int h = 0; h < H_; h++) {
        const __half* p0 = g_Muh + ((size_t)(b * H_ + h) * N_ + n) * MUP_;
        const __half* p1 = p0 + (size_t)BH_ * N_ * MUP_;
        float2 v0 = __half22float2(*(const __half2*)(p0 + 2 * lane));
        float2 v1 = __half22float2(*(const __half2*)(p1 + 2 * lane));
        mx[h] = v0.x + v1.x;
        my[h] = v0.y + v1.y;
        tv[h] = (lane == 0) ? (__half2float(p0[64]) + __half2float(p1[64])) : 0.f;
        ssv[h] = mx[h]*mx[h] + my[h]*my[h];
    }
    #pragma unroll
    for (int o = 16; o; o >>= 1) {
        #pragma unroll
        for (int h = 0; h < H_; h++)
            ssv[h] += __shfl_xor_sync(0xffffffffu, ssv[h], o);
    }
    #pragma unroll
    for (int h = 0; h < H_; h++)
        tv[h] = __shfl_sync(0xffffffffu, tv[h], 0);

    float ax = 0.f, ay = 0.f, at = 0.f;
    #pragma unroll
    for (int h = 0; h < H_; h++) {
        float neg = tv[h] * tv[h] - ssv[h];          // t^2 - ||s||^2
        float inv = rsqrtf(fmaxf(neg, EPS_));
        ax += mx[h] * inv; ay += my[h] * inv; at += tv[h] * inv;
    }
    float ss = ax * ax + ay * ay;
    #pragma unroll
    for (int o = 16; o; o >>= 1) ss += __shfl_xor_sync(0xffffffffu, ss, o);
    float neg2 = at * at - ss;
    float inv2 = rsqrtf(fmaxf(neg2, EPS_));
    float spx = ax * inv2, spy = ay * inv2;
    float ssp = ss * inv2 * inv2;                    // ||out_spatial||^2
    float t = sqrtf(1.0f + ssp);

    float* o_ = out + ((size_t)b * N_ + n) * AD_;
    o_[1 + 2 * lane] = spx;
    o_[2 + 2 * lane] = spy;
    if (lane == 0) o_[0] = t;
}

// ---------------- launch ------------------------------------------------------
extern "C" void kernel_launch(void* const* d_in, const int* in_sizes, int n_in,
                              void* d_out, int out_size)
{
    const float* x     = (const float*)d_in[0];
    const float* Wq    = (const float*)d_in[1];
    const float* Wk    = (const float*)d_in[2];
    const float* Wv    = (const float*)d_in[3];
    const float* bq    = (const float*)d_in[4];
    const float* bk    = (const float*)d_in[5];
    const float* bv    = (const float*)d_in[6];
    const float* scale = (const float*)d_in[7];
    float* out = (float*)d_out;

    cudaFuncSetAttribute(proj_kernel, cudaFuncAttributeMaxDynamicSharedMemorySize, PROJ_SMEM);
    cudaFuncSetAttribute(attn_kernel, cudaFuncAttributeMaxDynamicSharedMemorySize, ATTN_SMEM);

    prep_kernel<<<1024, 256>>>(x, Wq, Wk, Wv);
    proj_kernel<<<dim3(N_/128, H_, B_), 256, PROJ_SMEM>>>(bq, bk, bv);
    attn_kernel<<<dim3(N_/128, BH_, 2), 256, ATTN_SMEM>>>(scale);
    finalize_kernel<<<(B_*N_*32 + 255)/256, 256>>>(out);
}